// round 12
// baseline (speedup 1.0000x reference)
#include <cuda_runtime.h>

#define K       1024
#define THREADS 256
#define KA      8
#define T8      1038
#define NN8     256

#define BUF_ELEMS 16842752
__device__ float g_bufA[BUF_ELEMS];   // L2: 256 rows x 65548
__device__ float g_bufB[BUF_ELEMS];   // L4: 1024 rows x 16400

#define DECL_FILTERS \
    constexpr float LO[16] = { \
         0.0018899503327594609f, -0.0003029205147213668f, -0.01495225833704823f, \
         0.003808752013890615f,   0.049137179673607506f,  -0.027219029917056003f, \
        -0.05194583810770904f,    0.3644418948353314f,     0.7771857517005235f, \
         0.4813596512583722f,    -0.061273359067658524f,  -0.1432942383508097f, \
         0.007607487324917605f,   0.03169508781149298f,   -0.0005421323317911481f, \
        -0.0033824159510061256f }; \
    constexpr float HI[16] = { \
        -0.0033824159510061256f,  0.0005421323317911481f,  0.03169508781149298f, \
        -0.007607487324917605f,  -0.1432942383508097f,     0.061273359067658524f, \
         0.4813596512583722f,    -0.7771857517005235f,     0.3644418948353314f, \
         0.05194583810770904f,   -0.027219029917056003f,  -0.049137179673607506f, \
         0.003808752013890615f,   0.01495225833704823f,   -0.0003029205147213668f, \
        -0.0018899503327594609f };

template<int Q>
__device__ __forceinline__ void convN(const float* w, float* lo, float* hi) {
    DECL_FILTERS
    #pragma unroll
    for (int q = 0; q < Q; q++) {
        float a = 0.f, b = 0.f;
        #pragma unroll
        for (int i = 0; i < 16; i++) {
            float v = w[2 * q + i];
            a = fmaf(v, LO[i], a);
            b = fmaf(v, HI[i], b);
        }
        lo[q] = a; hi[q] = b;
    }
}

// 30-float window, base ≡ 2 mod 4 (s-2 is 16B-aligned): w[i] = s[i], i<30.
__device__ __forceinline__ void ldw30_2(const float* s, float* w) {
    float4 wv[8];
    const float4* p = (const float4*)(s - 2);
    #pragma unroll
    for (int i = 0; i < 8; i++) wv[i] = p[i];
    const float* f = (const float*)wv;
    #pragma unroll
    for (int i = 0; i < 30; i++) w[i] = f[i + 2];
}
// 30-float window, 16B-aligned base.
__device__ __forceinline__ void ldw30_0(const float* s, float* w) {
    float4 wv[8];
    const float4* p = (const float4*)s;
    #pragma unroll
    for (int i = 0; i < 8; i++) wv[i] = p[i];
    const float* f = (const float*)wv;
    #pragma unroll
    for (int i = 0; i < 30; i++) w[i] = f[i];
}

__device__ __forceinline__ int igray(int j) { j ^= j >> 1; j ^= j >> 2; j ^= j >> 4; return j; }

// ---------------- Mid kernel: two fused DWT levels, Q=8 ----------------
__global__ void __launch_bounds__(THREADS)
dwt_pair_mid(const float* __restrict__ ext_in, int in_sel, int out_sel, int lev,
             int t_in, int stride_in, int t_outA, int t_outB, int stride_out)
{
    __shared__ __align__(16) float s_in[4160];
    __shared__ __align__(16) float s_lo[2080];
    __shared__ __align__(16) float s_hi[2080];

    const float* in  = (in_sel == 0) ? ext_in : ((in_sel == 1) ? g_bufA : g_bufB);
    float*       outb = (out_sel == 1) ? g_bufA : g_bufB;

    int row = blockIdx.y;
    int k0  = blockIdx.x * K;
    const float* src = in + (size_t)row * stride_in;

    int mstart = 2 * k0 - 14;           if (mstart < 0) mstart = 0;
    int mend   = 2 * k0 + 2 * K - 1;    if (mend > t_outA - 1) mend = t_outA - 1;
    int aa = 2 * mstart - 16;
    bool bint = (2 * k0 - 14 >= 0) && (2 * (k0 + K - 1) + 1 <= t_outA - 1);

    if (bint && aa >= 0 && aa + 4140 <= t_in) {
        const float4* g  = (const float4*)(src + aa);   // aa = 4k0-44, 16B aligned
        float4*       s4 = (float4*)s_in;
        #pragma unroll
        for (int q = threadIdx.x; q < 1035; q += THREADS) s4[q] = g[q];
    } else {
        int nload = 2 * (mend - mstart) + 18;
        for (int idx = threadIdx.x; idx < nload; idx += THREADS) {
            int m = aa + idx;
            if (m < 0)      m = -m;
            if (m >= t_in)  m = 2 * t_in - 2 - m;
            s_in[idx] = src[m];
        }
    }
    __syncthreads();

    // ---- level A ----
    for (int m0 = mstart + KA * threadIdx.x; m0 <= mend; m0 += KA * THREADS) {
        float w[30];
        ldw30_2(s_in + 2 * (m0 - mstart) + 2, w);       // base ≡ 2 mod 16
        float lo[KA], hi[KA];
        convN<KA>(w, lo, hi);
        int cnt = mend - m0 + 1; if (cnt > KA) cnt = KA;
        int d = m0 - mstart;                            // multiple of 8
        if (cnt == KA) {
            *(float4*)(s_lo + d)     = make_float4(lo[0], lo[1], lo[2], lo[3]);
            *(float4*)(s_lo + d + 4) = make_float4(lo[4], lo[5], lo[6], lo[7]);
            *(float4*)(s_hi + d)     = make_float4(hi[0], hi[1], hi[2], hi[3]);
            *(float4*)(s_hi + d + 4) = make_float4(hi[4], hi[5], hi[6], hi[7]);
        } else {
            for (int q = 0; q < cnt; q++) { s_lo[d + q] = lo[q]; s_hi[d + q] = hi[q]; }
        }
    }
    __syncthreads();

    // ---- level B: 8 outputs per thread ----
    int c  = threadIdx.x >> 7;
    int s  = threadIdx.x & 127;
    int kk = k0 + 8 * s;
    if (kk >= t_outB) return;

    const float* A = c ? s_hi : s_lo;
    float lo2[8], hi2[8];
    if (bint) {
        float w[30];
        ldw30_0(A + 16 * s, w);                         // base ≡ 0 mod 16
        convN<8>(w, lo2, hi2);
    } else {
        float wf[30];
        #pragma unroll
        for (int i = 0; i < 30; i++) {
            int f = 2 * kk - 14 + i;
            if (f < 0)        f = -f;
            if (f >= t_outA)  f = 2 * t_outA - 2 - f;
            wf[i] = A[f - mstart];
        }
        convN<8>(wf, lo2, hi2);
    }

    int b    = row >> lev;
    int node = row & ((1 << lev) - 1);
    size_t r = ((size_t)((b << (lev + 2)) + 4 * node + 2 * c)) * stride_out + kk;
    if (kk + 8 <= t_outB) {
        *(float4*)(outb + r)                  = make_float4(lo2[0], lo2[1], lo2[2], lo2[3]);
        *(float4*)(outb + r + 4)              = make_float4(lo2[4], lo2[5], lo2[6], lo2[7]);
        *(float4*)(outb + r + stride_out)     = make_float4(hi2[0], hi2[1], hi2[2], hi2[3]);
        *(float4*)(outb + r + stride_out + 4) = make_float4(hi2[4], hi2[5], hi2[6], hi2[7]);
    } else {
        for (int q = 0; q < t_outB - kk; q++) {
            outb[r + q]              = lo2[q];
            outb[r + stride_out + q] = hi2[q];
        }
    }
}

// ---------------- Quad kernel: L4 -> L8 + permute/log/sign, Q=8 ----------------
#define STR_A 2264
#define STR_B 1140
#define STR_C 584
#define P1OFF 4560

template<int NR>
__device__ __forceinline__ void quad_pass(const float* __restrict__ inR, int inOrigin,
                                          int inStride, float* __restrict__ outR,
                                          int outStride, int Os, int Oe, int t_out,
                                          int tid)
{
    constexpr int TPR = 256 / NR;
    int r = tid / TPR;
    int s = tid % TPR;
    const float* inRow = inR + r * inStride;
    float* oLo = outR + (2 * r) * outStride;
    float* oHi = outR + (2 * r + 1) * outStride;
    int outOrigin = Os - 16;
    bool cb = (Os == 0);
    bool ct = (Oe == t_out - 1);

    for (int m0 = Os + 8 * s; m0 <= Oe; m0 += 8 * TPR) {
        float w[30];
        ldw30_2(inRow + (2 * m0 - 14 - inOrigin), w);
        float lo[8], hi[8];
        convN<8>(w, lo, hi);
        int d = m0 - outOrigin;                 // multiple of 8
        if (m0 + 7 <= Oe) {
            *(float4*)(oLo + d)     = make_float4(lo[0], lo[1], lo[2], lo[3]);
            *(float4*)(oLo + d + 4) = make_float4(lo[4], lo[5], lo[6], lo[7]);
            *(float4*)(oHi + d)     = make_float4(hi[0], hi[1], hi[2], hi[3]);
            *(float4*)(oHi + d + 4) = make_float4(hi[4], hi[5], hi[6], hi[7]);
        } else {
            for (int q = 0; q <= Oe - m0; q++) { oLo[d + q] = lo[q]; oHi[d + q] = hi[q]; }
        }
        if (cb && m0 <= 14) {
            #pragma unroll
            for (int q = 0; q < 8; q++) {
                int p = m0 + q;
                if (p >= 1 && p <= 14) { oLo[16 - p] = lo[q]; oHi[16 - p] = hi[q]; }
            }
        }
        if (ct && m0 + 7 >= t_out - 21) {
            #pragma unroll
            for (int q = 0; q < 8; q++) {
                int p = m0 + q;
                if (p >= t_out - 21 && p <= t_out - 2 && p <= Oe) {
                    int slot = 2 * (t_out - 1) - p - outOrigin;
                    oLo[slot] = lo[q]; oHi[slot] = hi[q];
                }
            }
        }
    }
}

__global__ void __launch_bounds__(THREADS)
dwt_quad(float* __restrict__ out)
{
    __shared__ __align__(16) float smem[9248];

    const int t4 = 16398, t5 = 8206, t6 = 4110, t7 = 2062, t8 = 1038;
    int r   = blockIdx.y;                 // L4 row 0..1023
    int j   = blockIdx.x;                 // tile 0..3
    int tid = threadIdx.x;

    int Ds = 264 * j;
    int De = min(Ds + 263, t8 - 1);
    int Cs = 2 * Ds - 14; if (Cs < 0) Cs = 0; Cs &= ~3;
    int Ce = min(t7 - 1, 2 * De + 1);
    int Bs = 2 * Cs - 14; if (Bs < 0) Bs = 0; Bs &= ~3;
    int Be = min(t6 - 1, 2 * Ce + 1);
    int As = 2 * Bs - 14; if (As < 0) As = 0; As &= ~3;
    int Ae = min(t5 - 1, 2 * Be + 1);
    int gx = 2 * As - 16;
    int xlen = 2 * Ae + 22 - gx;

    float* sx = smem;
    float* sA = smem + P1OFF;
    float* sB = smem;
    float* sC = smem + P1OFF;

    {
        const float* src = g_bufB + (size_t)r * 16400;
        int nv = (xlen + 3) >> 2;
        if (gx >= 0 && gx + 4 * nv <= t4) {
            const float4* g4 = (const float4*)(src + gx);
            float4* s4 = (float4*)sx;
            for (int q = tid; q < nv; q += THREADS) s4[q] = g4[q];
        } else {
            for (int idx = tid; idx < xlen; idx += THREADS) {
                int m = gx + idx;
                if (m < 0)     m = -m;
                if (m >= t4)   m = 2 * t4 - 2 - m;
                sx[idx] = src[m];
            }
        }
    }
    __syncthreads();

    quad_pass<1>(sx, gx, 0, sA, STR_A, As, Ae, t5, tid);          // L5
    __syncthreads();
    quad_pass<2>(sA, As - 16, STR_A, sB, STR_B, Bs, Be, t6, tid); // L6
    __syncthreads();
    quad_pass<4>(sB, Bs - 16, STR_B, sC, STR_C, Cs, Ce, t7, tid); // L7
    __syncthreads();

    // ---- L8 + permute/log/sign, 8 per thread ----
    int rc = tid >> 5;                    // C row 0..7
    int sc = tid & 31;
    const float* Crow = sC + rc * STR_C;
    int b    = r >> 4;
    int n4   = r & 15;
    int p0 = igray(n4 * 16 + 2 * rc);
    int p1 = igray(n4 * 16 + 2 * rc + 1);
    size_t ob = (size_t)b * (2 * NN8 * T8);
    const size_t SOFF = (size_t)NN8 * T8;
    float* L0 = out + ob + (size_t)p0 * T8;
    float* L1 = out + ob + (size_t)p1 * T8;

    for (int kk = Ds + 8 * sc; kk <= De; kk += 256) {
        float w[30];
        ldw30_2(Crow + (2 * kk + 2 - Cs), w);
        float lo[8], hi[8];
        convN<8>(w, lo, hi);
        if (kk + 7 <= De) {
            #pragma unroll
            for (int h = 0; h < 4; h++) {
                *(float2*)(L0 + kk + 2*h) = make_float2(__logf(fmaf(lo[2*h],   lo[2*h],   1e-12f)),
                                                        __logf(fmaf(lo[2*h+1], lo[2*h+1], 1e-12f)));
                *(float2*)(L1 + kk + 2*h) = make_float2(__logf(fmaf(hi[2*h],   hi[2*h],   1e-12f)),
                                                        __logf(fmaf(hi[2*h+1], hi[2*h+1], 1e-12f)));
                *(float2*)(L0 + SOFF + kk + 2*h) = make_float2(lo[2*h] < 0.f ? -1.f : 1.f,
                                                               lo[2*h+1] < 0.f ? -1.f : 1.f);
                *(float2*)(L1 + SOFF + kk + 2*h) = make_float2(hi[2*h] < 0.f ? -1.f : 1.f,
                                                               hi[2*h+1] < 0.f ? -1.f : 1.f);
            }
        } else {
            for (int q = 0; q <= De - kk; q++) {
                float x = lo[q], y = hi[q];
                L0[kk + q]        = __logf(fmaf(x, x, 1e-12f));
                L0[SOFF + kk + q] = (x < 0.f) ? -1.f : 1.f;
                L1[kk + q]        = __logf(fmaf(y, y, 1e-12f));
                L1[SOFF + kk + q] = (y < 0.f) ? -1.f : 1.f;
            }
        }
    }
}

extern "C" void kernel_launch(void* const* d_in, const int* in_sizes, int n_in_args,
                              void* d_out, int out_size) {
    (void)in_sizes; (void)n_in_args; (void)out_size;
    const float* in0 = (const float*)d_in[0];
    float* out = (float*)d_out;

    // t chain: 262144 -> 131079 -> 65547 -> 32781 -> 16398 -> 8206 -> 4110 -> 2062 -> 1038
    dim3 g0((65547 + K - 1) / K, 64);      // ext -> L2 (bufA, stride 65548)
    dwt_pair_mid<<<g0, THREADS>>>(in0, 0, 1, 0, 262144, 262144, 131079, 65547, 65548);
    dim3 g1((16398 + K - 1) / K, 256);     // L2 -> L4 (bufB, stride 16400)
    dwt_pair_mid<<<g1, THREADS>>>(in0, 1, 2, 2, 65547, 65548, 32781, 16398, 16400);
    // L4 -> L8 + permute/log/sign: 4 tiles x 1024 L4 rows
    dwt_quad<<<dim3(4, 1024), THREADS>>>(out);
}

// round 13
// speedup vs baseline: 1.5916x; 1.5916x over previous
#include <cuda_runtime.h>

#define K       512
#define THREADS 256
#define KA      4
#define T8      1038
#define NN8     256

#define BUF_ELEMS 16842752
__device__ float g_bufA[BUF_ELEMS];   // L2: 256 rows x 65548
__device__ float g_bufB[BUF_ELEMS];   // L4: 1024 rows x 16400

#define DECL_FILTERS \
    constexpr float LO[16] = { \
         0.0018899503327594609f, -0.0003029205147213668f, -0.01495225833704823f, \
         0.003808752013890615f,   0.049137179673607506f,  -0.027219029917056003f, \
        -0.05194583810770904f,    0.3644418948353314f,     0.7771857517005235f, \
         0.4813596512583722f,    -0.061273359067658524f,  -0.1432942383508097f, \
         0.007607487324917605f,   0.03169508781149298f,   -0.0005421323317911481f, \
        -0.0033824159510061256f }; \
    constexpr float HI[16] = { \
        -0.0033824159510061256f,  0.0005421323317911481f,  0.03169508781149298f, \
        -0.007607487324917605f,  -0.1432942383508097f,     0.061273359067658524f, \
         0.4813596512583722f,    -0.7771857517005235f,     0.3644418948353314f, \
         0.05194583810770904f,   -0.027219029917056003f,  -0.049137179673607506f, \
         0.003808752013890615f,   0.01495225833704823f,   -0.0003029205147213668f, \
        -0.0018899503327594609f };

template<int Q>
__device__ __forceinline__ void convN(const float* w, float* lo, float* hi) {
    DECL_FILTERS
    #pragma unroll
    for (int q = 0; q < Q; q++) {
        float a = 0.f, b = 0.f;
        #pragma unroll
        for (int i = 0; i < 16; i++) {
            float v = w[2 * q + i];
            a = fmaf(v, LO[i], a);
            b = fmaf(v, HI[i], b);
        }
        lo[q] = a; hi[q] = b;
    }
}

// 22-float window, base index ≡ 2 mod 4 (s-2 is 16B-aligned): w[i] = s[i].
__device__ __forceinline__ void ldwin2(const float* s, float* w) {
    float4 wv[6];
    const float4* p = (const float4*)(s - 2);
    #pragma unroll
    for (int i = 0; i < 6; i++) wv[i] = p[i];
    const float* f = (const float*)wv;
    #pragma unroll
    for (int i = 0; i < 22; i++) w[i] = f[i + 2];
}
// 22-float window, 16B-aligned base.
__device__ __forceinline__ void ldwin0(const float* s, float* w) {
    float4 wv[6];
    const float4* p = (const float4*)s;
    #pragma unroll
    for (int i = 0; i < 6; i++) wv[i] = p[i];
    const float* f = (const float*)wv;
    #pragma unroll
    for (int i = 0; i < 22; i++) w[i] = f[i];
}

__device__ __forceinline__ int igray(int j) { j ^= j >> 1; j ^= j >> 2; j ^= j >> 4; return j; }

// ---------------- Mid kernel (R11-proven, unchanged) ----------------
__global__ void __launch_bounds__(THREADS)
dwt_pair_mid(const float* __restrict__ ext_in, int in_sel, int out_sel, int lev,
             int t_in, int stride_in, int t_outA, int t_outB, int stride_out)
{
    __shared__ __align__(16) float s_in[2104];
    __shared__ __align__(16) float s_lo[1040];
    __shared__ __align__(16) float s_hi[1040];

    const float* in  = (in_sel == 0) ? ext_in : ((in_sel == 1) ? g_bufA : g_bufB);
    float*       outb = (out_sel == 1) ? g_bufA : g_bufB;

    int row = blockIdx.y;
    int k0  = blockIdx.x * K;
    const float* src = in + (size_t)row * stride_in;

    int mstart = 2 * k0 - 14;           if (mstart < 0) mstart = 0;
    int mend   = 2 * k0 + 2 * K - 1;    if (mend > t_outA - 1) mend = t_outA - 1;
    int aa = 2 * mstart - 16;
    bool bint = (2 * k0 - 14 >= 0) && (2 * (k0 + K - 1) + 1 <= t_outA - 1);

    if (bint && aa >= 0 && aa + 2092 <= t_in) {
        const float4* g  = (const float4*)(src + aa);
        float4*       s4 = (float4*)s_in;
        #pragma unroll
        for (int q = threadIdx.x; q < 523; q += THREADS) s4[q] = g[q];
    } else {
        int nload = 2 * (mend - mstart) + 18;
        for (int idx = threadIdx.x; idx < nload; idx += THREADS) {
            int m = aa + idx;
            if (m < 0)      m = -m;
            if (m >= t_in)  m = 2 * t_in - 2 - m;
            s_in[idx] = src[m];
        }
    }
    __syncthreads();

    for (int m0 = mstart + KA * threadIdx.x; m0 <= mend; m0 += KA * THREADS) {
        float w[22];
        ldwin2(s_in + 2 * (m0 - mstart) + 2, w);
        float lo[KA], hi[KA];
        convN<KA>(w, lo, hi);
        int cnt = mend - m0 + 1; if (cnt > KA) cnt = KA;
        int d = m0 - mstart;
        if (cnt == KA) {
            *(float4*)(s_lo + d) = make_float4(lo[0], lo[1], lo[2], lo[3]);
            *(float4*)(s_hi + d) = make_float4(hi[0], hi[1], hi[2], hi[3]);
        } else {
            for (int q = 0; q < cnt; q++) { s_lo[d + q] = lo[q]; s_hi[d + q] = hi[q]; }
        }
    }
    __syncthreads();

    int c  = threadIdx.x >> 7;
    int s  = threadIdx.x & 127;
    int kk = k0 + 4 * s;
    if (kk >= t_outB) return;

    const float* A = c ? s_hi : s_lo;
    float lo2[4], hi2[4];
    if (bint) {
        float w[22];
        ldwin0(A + 8 * s, w);
        convN<4>(w, lo2, hi2);
    } else {
        float wf[22];
        #pragma unroll
        for (int i = 0; i < 22; i++) {
            int f = 2 * kk - 14 + i;
            if (f < 0)        f = -f;
            if (f >= t_outA)  f = 2 * t_outA - 2 - f;
            wf[i] = A[f - mstart];
        }
        convN<4>(wf, lo2, hi2);
    }

    int b    = row >> lev;
    int node = row & ((1 << lev) - 1);
    size_t r = ((size_t)((b << (lev + 2)) + 4 * node + 2 * c)) * stride_out + kk;
    if (kk + 4 <= t_outB) {
        *(float4*)(outb + r)              = make_float4(lo2[0], lo2[1], lo2[2], lo2[3]);
        *(float4*)(outb + r + stride_out) = make_float4(hi2[0], hi2[1], hi2[2], hi2[3]);
    } else {
        for (int q = 0; q < t_outB - kk; q++) {
            outb[r + q]              = lo2[q];
            outb[r + stride_out + q] = hi2[q];
        }
    }
}

// ---------------- Quad kernel: L4 -> L8 + permute/log/sign ----------------
// 8 tiles of 132 L8 outputs; arena 4832 floats (19.3 KB) for 8 blocks/SM.
#define STR_A 1200
#define STR_B 600
#define STR_C 304
#define P1OFF 2400

template<int NR>
__device__ __forceinline__ void quad_pass(const float* __restrict__ inR, int inOrigin,
                                          int inStride, float* __restrict__ outR,
                                          int outStride, int Os, int Oe, int t_out,
                                          int tid)
{
    constexpr int TPR = 256 / NR;
    int r = tid / TPR;
    int s = tid % TPR;
    const float* inRow = inR + r * inStride;
    float* oLo = outR + (2 * r) * outStride;
    float* oHi = outR + (2 * r + 1) * outStride;
    int outOrigin = Os - 16;
    bool cb = (Os == 0);
    bool ct = (Oe == t_out - 1);

    for (int m0 = Os + 4 * s; m0 <= Oe; m0 += 4 * TPR) {
        float w[22];
        ldwin2(inRow + (2 * m0 - 14 - inOrigin), w);
        float lo[4], hi[4];
        convN<4>(w, lo, hi);
        int d = m0 - outOrigin;                 // multiple of 4
        if (m0 + 3 <= Oe) {
            *(float4*)(oLo + d) = make_float4(lo[0], lo[1], lo[2], lo[3]);
            *(float4*)(oHi + d) = make_float4(hi[0], hi[1], hi[2], hi[3]);
        } else {
            for (int q = 0; q <= Oe - m0; q++) { oLo[d + q] = lo[q]; oHi[d + q] = hi[q]; }
        }
        if (cb && m0 <= 14) {
            #pragma unroll
            for (int q = 0; q < 4; q++) {
                int p = m0 + q;
                if (p >= 1 && p <= 14) { oLo[16 - p] = lo[q]; oHi[16 - p] = hi[q]; }
            }
        }
        if (ct && m0 + 3 >= t_out - 21) {
            #pragma unroll
            for (int q = 0; q < 4; q++) {
                int p = m0 + q;
                if (p >= t_out - 21 && p <= t_out - 2 && p <= Oe) {
                    int slot = 2 * (t_out - 1) - p - outOrigin;
                    oLo[slot] = lo[q]; oHi[slot] = hi[q];
                }
            }
        }
    }
}

__global__ void __launch_bounds__(THREADS, 8)
dwt_quad(float* __restrict__ out)
{
    __shared__ __align__(16) float smem[4832];

    const int t4 = 16398, t5 = 8206, t6 = 4110, t7 = 2062, t8 = 1038;
    int r   = blockIdx.y;                 // L4 row 0..1023
    int j   = blockIdx.x;                 // tile 0..7
    int tid = threadIdx.x;

    int Ds = 132 * j;
    int De = min(Ds + 131, t8 - 1);
    int Cs = 2 * Ds - 14; if (Cs < 0) Cs = 0; Cs &= ~3;
    int Ce = min(t7 - 1, 2 * De + 1);
    int Bs = 2 * Cs - 14; if (Bs < 0) Bs = 0; Bs &= ~3;
    int Be = min(t6 - 1, 2 * Ce + 1);
    int As = 2 * Bs - 14; if (As < 0) As = 0; As &= ~3;
    int Ae = min(t5 - 1, 2 * Be + 1);
    int gx = 2 * As - 16;
    int xlen = 2 * Ae + 22 - gx;

    float* sx = smem;
    float* sA = smem + P1OFF;
    float* sB = smem;
    float* sC = smem + P1OFF;

    {
        const float* src = g_bufB + (size_t)r * 16400;
        int nv = (xlen + 3) >> 2;
        if (gx >= 0 && gx + 4 * nv <= t4) {
            const float4* g4 = (const float4*)(src + gx);
            float4* s4 = (float4*)sx;
            for (int q = tid; q < nv; q += THREADS) s4[q] = g4[q];
        } else {
            for (int idx = tid; idx < xlen; idx += THREADS) {
                int m = gx + idx;
                if (m < 0)     m = -m;
                if (m >= t4)   m = 2 * t4 - 2 - m;
                sx[idx] = src[m];
            }
        }
    }
    __syncthreads();

    quad_pass<1>(sx, gx, 0, sA, STR_A, As, Ae, t5, tid);          // L5
    __syncthreads();
    quad_pass<2>(sA, As - 16, STR_A, sB, STR_B, Bs, Be, t6, tid); // L6
    __syncthreads();
    quad_pass<4>(sB, Bs - 16, STR_B, sC, STR_C, Cs, Ce, t7, tid); // L7
    __syncthreads();

    // ---- L8 + permute/log/sign ----
    int rc = tid >> 5;                    // C row 0..7
    int sc = tid & 31;
    const float* Crow = sC + rc * STR_C;
    int b    = r >> 4;
    int n4   = r & 15;
    int p0 = igray(n4 * 16 + 2 * rc);
    int p1 = igray(n4 * 16 + 2 * rc + 1);
    size_t ob = (size_t)b * (2 * NN8 * T8);
    const size_t SOFF = (size_t)NN8 * T8;
    float* L0 = out + ob + (size_t)p0 * T8;
    float* L1 = out + ob + (size_t)p1 * T8;

    for (int kk = Ds + 4 * sc; kk <= De; kk += 128) {
        float w[22];
        ldwin2(Crow + (2 * kk + 2 - Cs), w);
        float lo[4], hi[4];
        convN<4>(w, lo, hi);
        if (kk + 3 <= De) {
            *(float2*)(L0 + kk)     = make_float2(__logf(fmaf(lo[0], lo[0], 1e-12f)),
                                                  __logf(fmaf(lo[1], lo[1], 1e-12f)));
            *(float2*)(L0 + kk + 2) = make_float2(__logf(fmaf(lo[2], lo[2], 1e-12f)),
                                                  __logf(fmaf(lo[3], lo[3], 1e-12f)));
            *(float2*)(L0 + SOFF + kk)     = make_float2(lo[0] < 0.f ? -1.f : 1.f,
                                                         lo[1] < 0.f ? -1.f : 1.f);
            *(float2*)(L0 + SOFF + kk + 2) = make_float2(lo[2] < 0.f ? -1.f : 1.f,
                                                         lo[3] < 0.f ? -1.f : 1.f);
            *(float2*)(L1 + kk)     = make_float2(__logf(fmaf(hi[0], hi[0], 1e-12f)),
                                                  __logf(fmaf(hi[1], hi[1], 1e-12f)));
            *(float2*)(L1 + kk + 2) = make_float2(__logf(fmaf(hi[2], hi[2], 1e-12f)),
                                                  __logf(fmaf(hi[3], hi[3], 1e-12f)));
            *(float2*)(L1 + SOFF + kk)     = make_float2(hi[0] < 0.f ? -1.f : 1.f,
                                                         hi[1] < 0.f ? -1.f : 1.f);
            *(float2*)(L1 + SOFF + kk + 2) = make_float2(hi[2] < 0.f ? -1.f : 1.f,
                                                         hi[3] < 0.f ? -1.f : 1.f);
        } else {
            for (int q = 0; q <= De - kk; q++) {
                float x = lo[q], y = hi[q];
                L0[kk + q]        = __logf(fmaf(x, x, 1e-12f));
                L0[SOFF + kk + q] = (x < 0.f) ? -1.f : 1.f;
                L1[kk + q]        = __logf(fmaf(y, y, 1e-12f));
                L1[SOFF + kk + q] = (y < 0.f) ? -1.f : 1.f;
            }
        }
    }
}

extern "C" void kernel_launch(void* const* d_in, const int* in_sizes, int n_in_args,
                              void* d_out, int out_size) {
    (void)in_sizes; (void)n_in_args; (void)out_size;
    const float* in0 = (const float*)d_in[0];
    float* out = (float*)d_out;

    // t chain: 262144 -> 131079 -> 65547 -> 32781 -> 16398 -> 8206 -> 4110 -> 2062 -> 1038
    dim3 g0((65547 + K - 1) / K, 64);      // ext -> L2 (bufA, stride 65548)
    dwt_pair_mid<<<g0, THREADS>>>(in0, 0, 1, 0, 262144, 262144, 131079, 65547, 65548);
    dim3 g1((16398 + K - 1) / K, 256);     // L2 -> L4 (bufB, stride 16400)
    dwt_pair_mid<<<g1, THREADS>>>(in0, 1, 2, 2, 65547, 65548, 32781, 16398, 16400);
    // L4 -> L8 + permute/log/sign: 8 tiles x 1024 L4 rows
    dwt_quad<<<dim3(8, 1024), THREADS>>>(out);
}

// round 15
// speedup vs baseline: 1.8473x; 1.1607x over previous
#include <cuda_runtime.h>

#define THREADS 256
#define T8      1038
#define NN8     256

// L4 scratch: 1024 rows x 16400 = 16,793,600 floats.
__device__ float g_bufB[16793600];

#define DECL_FILTERS \
    constexpr float LO[16] = { \
         0.0018899503327594609f, -0.0003029205147213668f, -0.01495225833704823f, \
         0.003808752013890615f,   0.049137179673607506f,  -0.027219029917056003f, \
        -0.05194583810770904f,    0.3644418948353314f,     0.7771857517005235f, \
         0.4813596512583722f,    -0.061273359067658524f,  -0.1432942383508097f, \
         0.007607487324917605f,   0.03169508781149298f,   -0.0005421323317911481f, \
        -0.0033824159510061256f }; \
    constexpr float HI[16] = { \
        -0.0033824159510061256f,  0.0005421323317911481f,  0.03169508781149298f, \
        -0.007607487324917605f,  -0.1432942383508097f,     0.061273359067658524f, \
         0.4813596512583722f,    -0.7771857517005235f,     0.3644418948353314f, \
         0.05194583810770904f,   -0.027219029917056003f,  -0.049137179673607506f, \
         0.003808752013890615f,   0.01495225833704823f,   -0.0003029205147213668f, \
        -0.0018899503327594609f };

template<int Q>
__device__ __forceinline__ void convN(const float* w, float* lo, float* hi) {
    DECL_FILTERS
    #pragma unroll
    for (int q = 0; q < Q; q++) {
        float a = 0.f, b = 0.f;
        #pragma unroll
        for (int i = 0; i < 16; i++) {
            float v = w[2 * q + i];
            a = fmaf(v, LO[i], a);
            b = fmaf(v, HI[i], b);
        }
        lo[q] = a; hi[q] = b;
    }
}

// 22-float window, base index ≡ 2 mod 4 (s-2 is 16B-aligned): w[i] = s[i].
__device__ __forceinline__ void ldwin2(const float* s, float* w) {
    float4 wv[6];
    const float4* p = (const float4*)(s - 2);
    #pragma unroll
    for (int i = 0; i < 6; i++) wv[i] = p[i];
    const float* f = (const float*)wv;
    #pragma unroll
    for (int i = 0; i < 22; i++) w[i] = f[i + 2];
}

__device__ __forceinline__ int igray(int j) { j ^= j >> 1; j ^= j >> 2; j ^= j >> 4; return j; }

// Shared 2-level-cascade machinery (R11-proven geometry, tile = 264 outputs).
#define STR_A 2248
#define STR_B 1140
#define STR_C 584
#define P1OFF 4560

template<int NR>
__device__ __forceinline__ void quad_pass(const float* __restrict__ inR, int inOrigin,
                                          int inStride, float* __restrict__ outR,
                                          int outStride, int Os, int Oe, int t_out,
                                          int tid)
{
    constexpr int TPR = 256 / NR;
    int r = tid / TPR;
    int s = tid % TPR;
    const float* inRow = inR + r * inStride;
    float* oLo = outR + (2 * r) * outStride;
    float* oHi = outR + (2 * r + 1) * outStride;
    int outOrigin = Os - 16;
    bool cb = (Os == 0);
    bool ct = (Oe == t_out - 1);

    for (int m0 = Os + 4 * s; m0 <= Oe; m0 += 4 * TPR) {
        float w[22];
        ldwin2(inRow + (2 * m0 - 14 - inOrigin), w);
        float lo[4], hi[4];
        convN<4>(w, lo, hi);
        int d = m0 - outOrigin;                 // multiple of 4
        if (m0 + 3 <= Oe) {
            *(float4*)(oLo + d) = make_float4(lo[0], lo[1], lo[2], lo[3]);
            *(float4*)(oHi + d) = make_float4(hi[0], hi[1], hi[2], hi[3]);
        } else {
            for (int q = 0; q <= Oe - m0; q++) { oLo[d + q] = lo[q]; oHi[d + q] = hi[q]; }
        }
        if (cb && m0 <= 14) {
            #pragma unroll
            for (int q = 0; q < 4; q++) {
                int p = m0 + q;
                if (p >= 1 && p <= 14) { oLo[16 - p] = lo[q]; oHi[16 - p] = hi[q]; }
            }
        }
        if (ct && m0 + 3 >= t_out - 21) {
            #pragma unroll
            for (int q = 0; q < 4; q++) {
                int p = m0 + q;
                if (p >= t_out - 21 && p <= t_out - 2 && p <= Oe) {
                    int slot = 2 * (t_out - 1) - p - outOrigin;
                    oLo[slot] = lo[q]; oHi[slot] = hi[q];
                }
            }
        }
    }
}

// ---------------- Front kernel: L0 -> L4, writes g_bufB ----------------
__global__ void __launch_bounds__(THREADS)
dwt_front(const float* __restrict__ ext_in)
{
    __shared__ __align__(16) float smem[9232];

    const int t0 = 262144, t1 = 131079, t2 = 65547, t3 = 32781, t4 = 16398;
    int r   = blockIdx.y;                 // L0 row (batch) 0..63
    int j   = blockIdx.x;                 // tile 0..62
    int tid = threadIdx.x;

    int Ds = 264 * j;
    int De = min(Ds + 263, t4 - 1);
    int Cs = 2 * Ds - 14; if (Cs < 0) Cs = 0; Cs &= ~3;
    int Ce = min(t3 - 1, 2 * De + 1);
    int Bs = 2 * Cs - 14; if (Bs < 0) Bs = 0; Bs &= ~3;
    int Be = min(t2 - 1, 2 * Ce + 1);
    int As = 2 * Bs - 14; if (As < 0) As = 0; As &= ~3;
    int Ae = min(t1 - 1, 2 * Be + 1);
    int gx = 2 * As - 16;
    int xlen = 2 * Ae + 22 - gx;

    float* sx = smem;
    float* sA = smem + P1OFF;
    float* sB = smem;
    float* sC = smem + P1OFF;

    {
        const float* src = ext_in + (size_t)r * t0;
        int nv = (xlen + 3) >> 2;
        if (gx >= 0 && gx + 4 * nv <= t0) {
            const float4* g4 = (const float4*)(src + gx);   // gx = 4224j-240, 16-aligned
            float4* s4 = (float4*)sx;
            for (int q = tid; q < nv; q += THREADS) s4[q] = g4[q];
        } else {
            for (int idx = tid; idx < xlen; idx += THREADS) {
                int m = gx + idx;
                if (m < 0)     m = -m;
                if (m >= t0)   m = 2 * t0 - 2 - m;
                sx[idx] = src[m];
            }
        }
    }
    __syncthreads();

    quad_pass<1>(sx, gx, 0, sA, STR_A, As, Ae, t1, tid);          // L1
    __syncthreads();
    quad_pass<2>(sA, As - 16, STR_A, sB, STR_B, Bs, Be, t2, tid); // L2
    __syncthreads();
    quad_pass<4>(sB, Bs - 16, STR_B, sC, STR_C, Cs, Ce, t3, tid); // L3
    __syncthreads();

    // ---- L4: 8 C rows -> 16 L4 rows, write gmem ----
    int rc = tid >> 5;                    // C row 0..7
    int sc = tid & 31;
    const float* Crow = sC + rc * STR_C;
    float* R0 = g_bufB + (size_t)(r * 16 + 2 * rc) * 16400;
    float* R1 = R0 + 16400;

    for (int kk = Ds + 4 * sc; kk <= De; kk += 128) {
        float w[22];
        ldwin2(Crow + (2 * kk + 2 - Cs), w);
        float lo[4], hi[4];
        convN<4>(w, lo, hi);
        if (kk + 3 <= De) {
            *(float4*)(R0 + kk) = make_float4(lo[0], lo[1], lo[2], lo[3]);
            *(float4*)(R1 + kk) = make_float4(hi[0], hi[1], hi[2], hi[3]);
        } else {
            for (int q = 0; q <= De - kk; q++) { R0[kk + q] = lo[q]; R1[kk + q] = hi[q]; }
        }
    }
}

// ---------------- Quad kernel: L4 -> L8 + permute/log/sign (R11 exact) ----------------
__global__ void __launch_bounds__(THREADS)
dwt_quad(float* __restrict__ out)
{
    __shared__ __align__(16) float smem[9232];

    const int t4 = 16398, t5 = 8206, t6 = 4110, t7 = 2062, t8 = 1038;
    int r   = blockIdx.y;                 // L4 row 0..1023
    int j   = blockIdx.x;                 // tile 0..3
    int tid = threadIdx.x;

    int Ds = 264 * j;
    int De = min(Ds + 263, t8 - 1);
    int Cs = 2 * Ds - 14; if (Cs < 0) Cs = 0; Cs &= ~3;
    int Ce = min(t7 - 1, 2 * De + 1);
    int Bs = 2 * Cs - 14; if (Bs < 0) Bs = 0; Bs &= ~3;
    int Be = min(t6 - 1, 2 * Ce + 1);
    int As = 2 * Bs - 14; if (As < 0) As = 0; As &= ~3;
    int Ae = min(t5 - 1, 2 * Be + 1);
    int gx = 2 * As - 16;
    int xlen = 2 * Ae + 22 - gx;

    float* sx = smem;
    float* sA = smem + P1OFF;
    float* sB = smem;
    float* sC = smem + P1OFF;

    {
        const float* src = g_bufB + (size_t)r * 16400;
        int nv = (xlen + 3) >> 2;
        if (gx >= 0 && gx + 4 * nv <= t4) {
            const float4* g4 = (const float4*)(src + gx);
            float4* s4 = (float4*)sx;
            for (int q = tid; q < nv; q += THREADS) s4[q] = g4[q];
        } else {
            for (int idx = tid; idx < xlen; idx += THREADS) {
                int m = gx + idx;
                if (m < 0)     m = -m;
                if (m >= t4)   m = 2 * t4 - 2 - m;
                sx[idx] = src[m];
            }
        }
    }
    __syncthreads();

    quad_pass<1>(sx, gx, 0, sA, STR_A, As, Ae, t5, tid);          // L5
    __syncthreads();
    quad_pass<2>(sA, As - 16, STR_A, sB, STR_B, Bs, Be, t6, tid); // L6
    __syncthreads();
    quad_pass<4>(sB, Bs - 16, STR_B, sC, STR_C, Cs, Ce, t7, tid); // L7
    __syncthreads();

    // ---- L8 + permute/log/sign ----
    int rc = tid >> 5;                    // C row 0..7
    int sc = tid & 31;
    const float* Crow = sC + rc * STR_C;
    int b    = r >> 4;
    int n4   = r & 15;
    int p0 = igray(n4 * 16 + 2 * rc);
    int p1 = igray(n4 * 16 + 2 * rc + 1);
    size_t ob = (size_t)b * (2 * NN8 * T8);
    const size_t SOFF = (size_t)NN8 * T8;
    float* L0 = out + ob + (size_t)p0 * T8;
    float* L1 = out + ob + (size_t)p1 * T8;

    for (int kk = Ds + 4 * sc; kk <= De; kk += 128) {
        float w[22];
        ldwin2(Crow + (2 * kk + 2 - Cs), w);
        float lo[4], hi[4];
        convN<4>(w, lo, hi);
        if (kk + 3 <= De) {
            *(float2*)(L0 + kk)     = make_float2(__logf(fmaf(lo[0], lo[0], 1e-12f)),
                                                  __logf(fmaf(lo[1], lo[1], 1e-12f)));
            *(float2*)(L0 + kk + 2) = make_float2(__logf(fmaf(lo[2], lo[2], 1e-12f)),
                                                  __logf(fmaf(lo[3], lo[3], 1e-12f)));
            *(float2*)(L0 + SOFF + kk)     = make_float2(lo[0] < 0.f ? -1.f : 1.f,
                                                         lo[1] < 0.f ? -1.f : 1.f);
            *(float2*)(L0 + SOFF + kk + 2) = make_float2(lo[2] < 0.f ? -1.f : 1.f,
                                                         lo[3] < 0.f ? -1.f : 1.f);
            *(float2*)(L1 + kk)     = make_float2(__logf(fmaf(hi[0], hi[0], 1e-12f)),
                                                  __logf(fmaf(hi[1], hi[1], 1e-12f)));
            *(float2*)(L1 + kk + 2) = make_float2(__logf(fmaf(hi[2], hi[2], 1e-12f)),
                                                  __logf(fmaf(hi[3], hi[3], 1e-12f)));
            *(float2*)(L1 + SOFF + kk)     = make_float2(hi[0] < 0.f ? -1.f : 1.f,
                                                         hi[1] < 0.f ? -1.f : 1.f);
            *(float2*)(L1 + SOFF + kk + 2) = make_float2(hi[2] < 0.f ? -1.f : 1.f,
                                                         hi[3] < 0.f ? -1.f : 1.f);
        } else {
            for (int q = 0; q <= De - kk; q++) {
                float x = lo[q], y = hi[q];
                L0[kk + q]        = __logf(fmaf(x, x, 1e-12f));
                L0[SOFF + kk + q] = (x < 0.f) ? -1.f : 1.f;
                L1[kk + q]        = __logf(fmaf(y, y, 1e-12f));
                L1[SOFF + kk + q] = (y < 0.f) ? -1.f : 1.f;
            }
        }
    }
}

extern "C" void kernel_launch(void* const* d_in, const int* in_sizes, int n_in_args,
                              void* d_out, int out_size) {
    (void)in_sizes; (void)n_in_args; (void)out_size;
    const float* in0 = (const float*)d_in[0];
    float* out = (float*)d_out;

    // L0 -> L4: 63 tiles x 64 rows
    dwt_front<<<dim3(63, 64), THREADS>>>(in0);
    // L4 -> L8 + permute/log/sign: 4 tiles x 1024 rows
    dwt_quad<<<dim3(4, 1024), THREADS>>>(out);
}